// round 1
// baseline (speedup 1.0000x reference)
#include <cuda_runtime.h>
#include <math.h>

// Problem constants
#define BATCH   512
#define N_IN    128
#define N_OUT   256
#define KDEG    3
#define NKNOT   10          // G + 2K + 1
#define NBASIS  6           // G + K
#define NFEAT   7           // 6 basis + swish residual
#define KDIM    (N_IN*NFEAT)    // 896

// Scratch (device globals — no allocation allowed)
__device__ float g_F[BATCH * KDIM];     // features, row-major [b][k], k = i*7+m
__device__ float g_W[KDIM * N_OUT];     // weights,  row-major [k][o], pre-scaled by 1/128

// ---------------------------------------------------------------------------
// Kernel 0: zero the output (poisoned by harness; atomic epilogue accumulates)
// ---------------------------------------------------------------------------
__global__ void zero_kernel(float* __restrict__ out) {
    int idx = blockIdx.x * blockDim.x + threadIdx.x;
    if (idx < BATCH * N_OUT) out[idx] = 0.0f;
}

// ---------------------------------------------------------------------------
// Kernel 1: features. One thread per (b,i): Cox-de Boor degree-3 basis (6
// values) over the shared knot row + swish residual. Grid rows are identical
// (reference tiles row 0), so every thread reads grid[0..9].
// ---------------------------------------------------------------------------
__global__ void feature_kernel(const float* __restrict__ x,
                               const float* __restrict__ grid) {
    int idx = blockIdx.x * blockDim.x + threadIdx.x;  // b*N_IN + i
    if (idx >= BATCH * N_IN) return;

    float g[NKNOT];
    #pragma unroll
    for (int t = 0; t < NKNOT; t++) g[t] = grid[t];   // row 0

    float xv = x[idx];

    // degree-0 indicators over the 9 knot intervals
    float basis[NKNOT - 1];
    #pragma unroll
    for (int t = 0; t < NKNOT - 1; t++)
        basis[t] = (xv >= g[t] && xv < g[t + 1]) ? 1.0f : 0.0f;

    // Cox-de Boor recursion, in-place ascending (reads old t, t+1)
    #pragma unroll
    for (int kk = 1; kk <= KDEG; kk++) {
        #pragma unroll
        for (int t = 0; t < (NKNOT - 1) - kk; t++) {
            float left  = (xv - g[t]) / (g[t + kk] - g[t]) * basis[t];
            float right = (g[t + kk + 1] - xv) / (g[t + kk + 1] - g[t + 1]) * basis[t + 1];
            basis[t] = left + right;
        }
    }

    int b = idx >> 7;          // / N_IN
    int i = idx & (N_IN - 1);
    float* dst = &g_F[b * KDIM + i * NFEAT];
    #pragma unroll
    for (int m = 0; m < NBASIS; m++) dst[m] = basis[m];
    dst[NBASIS] = xv / (1.0f + expf(-xv));   // swish(x) = x*sigmoid(x)
}

// ---------------------------------------------------------------------------
// Kernel 2: build weight matrix W[k][o], k = i*7+m.
// W = c_spl[j]*c_basis[j,m] (m<6) or c_res[j] (m=6), scaled by 1/N_IN.
// Thread per output element -> coalesced writes.
// ---------------------------------------------------------------------------
__global__ void weight_kernel(const float* __restrict__ c_basis,
                              const float* __restrict__ c_spl,
                              const float* __restrict__ c_res) {
    int idx = blockIdx.x * blockDim.x + threadIdx.x;  // k*N_OUT + o
    if (idx >= KDIM * N_OUT) return;
    int k = idx >> 8;          // / N_OUT
    int o = idx & (N_OUT - 1);
    int i = k / NFEAT;
    int m = k - i * NFEAT;
    int j = o * N_IN + i;
    float w = (m < NBASIS) ? (c_spl[j] * c_basis[j * NBASIS + m]) : c_res[j];
    g_W[idx] = w * (1.0f / N_IN);
}

// ---------------------------------------------------------------------------
// Kernel 3: fp32 SGEMM  out(512x256) += F(512x896) @ W(896x256)
// BM=64, BN=64, BK=16, split-K=4 (slice 224) -> 8*4*4 = 128 CTAs (one wave).
// 256 threads, 4x4 register microtile, atomicAdd epilogue.
// ---------------------------------------------------------------------------
#define BM 64
#define BN 64
#define BK 16
#define KSPLIT 4
#define KSLICE (KDIM / KSPLIT)   // 224

__global__ void __launch_bounds__(256, 1)
gemm_kernel(float* __restrict__ out) {
    __shared__ float As[BK][BM];   // transposed A tile: As[k][m]
    __shared__ float Bs[BK][BN];   // Bs[k][n]

    const int m0 = blockIdx.x * BM;
    const int n0 = blockIdx.y * BN;
    const int k0 = blockIdx.z * KSLICE;

    const int tid = threadIdx.x;
    const int tx = tid & 15;       // n direction (16)
    const int ty = tid >> 4;       // m direction (16)

    // load mappings (one float4 per thread per tile)
    const int a_row  = tid >> 2;   // 0..63
    const int a_col4 = tid & 3;    // 0..3  (16 cols = 4 float4)
    const int b_row  = tid >> 4;   // 0..15
    const int b_col4 = tid & 15;   // 0..15 (64 cols = 16 float4)

    float acc[4][4] = {};

    for (int kt = 0; kt < KSLICE; kt += BK) {
        float4 av = *(const float4*)&g_F[(m0 + a_row) * KDIM + (k0 + kt) + a_col4 * 4];
        As[a_col4 * 4 + 0][a_row] = av.x;
        As[a_col4 * 4 + 1][a_row] = av.y;
        As[a_col4 * 4 + 2][a_row] = av.z;
        As[a_col4 * 4 + 3][a_row] = av.w;

        float4 bv = *(const float4*)&g_W[(k0 + kt + b_row) * N_OUT + n0 + b_col4 * 4];
        *(float4*)&Bs[b_row][b_col4 * 4] = bv;

        __syncthreads();

        #pragma unroll
        for (int kk = 0; kk < BK; kk++) {
            float4 a4 = *(const float4*)&As[kk][ty * 4];
            float4 b4 = *(const float4*)&Bs[kk][tx * 4];
            float a[4] = {a4.x, a4.y, a4.z, a4.w};
            float b[4] = {b4.x, b4.y, b4.z, b4.w};
            #pragma unroll
            for (int u = 0; u < 4; u++)
                #pragma unroll
                for (int v = 0; v < 4; v++)
                    acc[u][v] = fmaf(a[u], b[v], acc[u][v]);
        }

        __syncthreads();
    }

    #pragma unroll
    for (int u = 0; u < 4; u++) {
        int row = m0 + ty * 4 + u;
        #pragma unroll
        for (int v = 0; v < 4; v++) {
            atomicAdd(&out[row * N_OUT + n0 + tx * 4 + v], acc[u][v]);
        }
    }
}

// ---------------------------------------------------------------------------
// Launch
// ---------------------------------------------------------------------------
extern "C" void kernel_launch(void* const* d_in, const int* in_sizes, int n_in,
                              void* d_out, int out_size) {
    const float* x       = (const float*)d_in[0];   // (512,128)
    const float* grid    = (const float*)d_in[1];   // (32768,10), rows identical
    const float* c_basis = (const float*)d_in[2];   // (32768,6)
    const float* c_spl   = (const float*)d_in[3];   // (32768,)
    const float* c_res   = (const float*)d_in[4];   // (32768,)
    float* out = (float*)d_out;                     // (512,256)

    zero_kernel<<<(BATCH * N_OUT + 255) / 256, 256>>>(out);
    feature_kernel<<<(BATCH * N_IN + 255) / 256, 256>>>(x, grid);
    weight_kernel<<<(KDIM * N_OUT + 255) / 256, 256>>>(c_basis, c_spl, c_res);

    dim3 gdim(BATCH / BM, N_OUT / BN, KSPLIT);  // 8 x 4 x 4 = 128 CTAs
    gemm_kernel<<<gdim, 256>>>(out);
}

// round 2
// speedup vs baseline: 1.2240x; 1.2240x over previous
#include <cuda_runtime.h>
#include <math.h>

// Problem constants
#define BATCH   512
#define N_IN    128
#define N_OUT   256
#define KDEG    3
#define NKNOT   10          // G + 2K + 1
#define NBASIS  6           // G + K
#define NFEAT   7           // 6 basis + swish residual
#define KDIM    (N_IN*NFEAT)    // 896

#define OUT_ELEMS (BATCH * N_OUT)        // 131072
#define W_ELEMS   (KDIM * N_OUT)         // 229376
#define F_ELEMS   (BATCH * N_IN)         // 65536
#define PREP_TOTAL (OUT_ELEMS + W_ELEMS + F_ELEMS)

// Scratch (device globals — no allocation allowed)
__device__ float g_F[BATCH * KDIM];     // features, row-major [b][k], k = i*7+m
__device__ float g_W[KDIM * N_OUT];     // weights,  row-major [k][o], pre-scaled by 1/128

// ---------------------------------------------------------------------------
// Fused prep kernel: range-partitioned over [zero out | build W | build F]
// ---------------------------------------------------------------------------
__global__ void prep_kernel(const float* __restrict__ x,
                            const float* __restrict__ grid,
                            const float* __restrict__ c_basis,
                            const float* __restrict__ c_spl,
                            const float* __restrict__ c_res,
                            float* __restrict__ out) {
    int idx = blockIdx.x * blockDim.x + threadIdx.x;

    if (idx < OUT_ELEMS) {                       // --- zero output ---
        out[idx] = 0.0f;
        return;
    }
    idx -= OUT_ELEMS;

    if (idx < W_ELEMS) {                         // --- weight matrix ---
        int k = idx >> 8;          // / N_OUT
        int o = idx & (N_OUT - 1);
        int i = k / NFEAT;
        int m = k - i * NFEAT;
        int j = o * N_IN + i;
        float w = (m < NBASIS) ? (c_spl[j] * c_basis[j * NBASIS + m]) : c_res[j];
        g_W[idx] = w * (1.0f / N_IN);
        return;
    }
    idx -= W_ELEMS;

    if (idx < F_ELEMS) {                         // --- features ---
        float g[NKNOT];
        #pragma unroll
        for (int t = 0; t < NKNOT; t++) g[t] = grid[t];   // all grid rows identical

        float xv = x[idx];

        float basis[NKNOT - 1];
        #pragma unroll
        for (int t = 0; t < NKNOT - 1; t++)
            basis[t] = (xv >= g[t] && xv < g[t + 1]) ? 1.0f : 0.0f;

        #pragma unroll
        for (int kk = 1; kk <= KDEG; kk++) {
            #pragma unroll
            for (int t = 0; t < (NKNOT - 1) - kk; t++) {
                float left  = (xv - g[t]) / (g[t + kk] - g[t]) * basis[t];
                float right = (g[t + kk + 1] - xv) / (g[t + kk + 1] - g[t + 1]) * basis[t + 1];
                basis[t] = left + right;
            }
        }

        int b = idx >> 7;          // / N_IN
        int i = idx & (N_IN - 1);
        float* dst = &g_F[b * KDIM + i * NFEAT];
        #pragma unroll
        for (int m = 0; m < NBASIS; m++) dst[m] = basis[m];
        dst[NBASIS] = xv / (1.0f + expf(-xv));   // swish
    }
}

// ---------------------------------------------------------------------------
// fp32 SGEMM  out(512x256) += F(512x896) @ W(896x256)
// BM=64, BN=64, BK=16, split-K=8 (slice 112) -> 8*4*8 = 256 CTAs.
// 256 threads, 4x4 register microtile, double-buffered smem, atomic epilogue.
// ---------------------------------------------------------------------------
#define BM 64
#define BN 64
#define BK 16
#define KSPLIT 8
#define KSLICE (KDIM / KSPLIT)   // 112
#define NTILES (KSLICE / BK)     // 7

__global__ void __launch_bounds__(256, 2)
gemm_kernel(float* __restrict__ out) {
    __shared__ float As[2][BK][BM];   // transposed A tile: As[buf][k][m]
    __shared__ float Bs[2][BK][BN];   // Bs[buf][k][n]

    const int m0 = blockIdx.x * BM;
    const int n0 = blockIdx.y * BN;
    const int k0 = blockIdx.z * KSLICE;

    const int tid = threadIdx.x;
    const int tx = tid & 15;       // n direction (16)
    const int ty = tid >> 4;       // m direction (16)

    // load mappings (one float4 per thread per tile)
    const int a_row  = tid >> 2;   // 0..63
    const int a_col4 = tid & 3;    // 0..3  (16 cols = 4 float4)
    const int b_row  = tid >> 4;   // 0..15
    const int b_col4 = tid & 15;   // 0..15 (64 cols = 16 float4)

    const float* aptr = &g_F[(m0 + a_row) * KDIM + k0 + a_col4 * 4];
    const float* bptr = &g_W[(k0 + b_row) * N_OUT + n0 + b_col4 * 4];

    float acc[4][4] = {};

    // preload tile 0 into buffer 0
    float4 av = *(const float4*)aptr;
    float4 bv = *(const float4*)bptr;
    As[0][a_col4 * 4 + 0][a_row] = av.x;
    As[0][a_col4 * 4 + 1][a_row] = av.y;
    As[0][a_col4 * 4 + 2][a_row] = av.z;
    As[0][a_col4 * 4 + 3][a_row] = av.w;
    *(float4*)&Bs[0][b_row][b_col4 * 4] = bv;
    __syncthreads();

    int buf = 0;
    #pragma unroll
    for (int t = 0; t < NTILES; t++) {
        // prefetch next tile into registers (no stall: consumed after compute)
        if (t + 1 < NTILES) {
            av = *(const float4*)(aptr + (t + 1) * BK);
            bv = *(const float4*)(bptr + (t + 1) * BK * N_OUT);
        }

        // compute current tile
        #pragma unroll
        for (int kk = 0; kk < BK; kk++) {
            float4 a4 = *(const float4*)&As[buf][kk][ty * 4];
            float4 b4 = *(const float4*)&Bs[buf][kk][tx * 4];
            float a[4] = {a4.x, a4.y, a4.z, a4.w};
            float b[4] = {b4.x, b4.y, b4.z, b4.w};
            #pragma unroll
            for (int u = 0; u < 4; u++)
                #pragma unroll
                for (int v = 0; v < 4; v++)
                    acc[u][v] = fmaf(a[u], b[v], acc[u][v]);
        }

        // stage next tile into the other buffer (safe: nobody reads it yet)
        if (t + 1 < NTILES) {
            int nb = buf ^ 1;
            As[nb][a_col4 * 4 + 0][a_row] = av.x;
            As[nb][a_col4 * 4 + 1][a_row] = av.y;
            As[nb][a_col4 * 4 + 2][a_row] = av.z;
            As[nb][a_col4 * 4 + 3][a_row] = av.w;
            *(float4*)&Bs[nb][b_row][b_col4 * 4] = bv;
            __syncthreads();
            buf = nb;
        }
    }

    #pragma unroll
    for (int u = 0; u < 4; u++) {
        int row = m0 + ty * 4 + u;
        #pragma unroll
        for (int v = 0; v < 4; v++) {
            atomicAdd(&out[row * N_OUT + n0 + tx * 4 + v], acc[u][v]);
        }
    }
}

// ---------------------------------------------------------------------------
// Launch
// ---------------------------------------------------------------------------
extern "C" void kernel_launch(void* const* d_in, const int* in_sizes, int n_in,
                              void* d_out, int out_size) {
    const float* x       = (const float*)d_in[0];   // (512,128)
    const float* grid    = (const float*)d_in[1];   // (32768,10), rows identical
    const float* c_basis = (const float*)d_in[2];   // (32768,6)
    const float* c_spl   = (const float*)d_in[3];   // (32768,)
    const float* c_res   = (const float*)d_in[4];   // (32768,)
    float* out = (float*)d_out;                     // (512,256)

    prep_kernel<<<(PREP_TOTAL + 255) / 256, 256>>>(x, grid, c_basis, c_spl, c_res, out);

    dim3 gdim(BATCH / BM, N_OUT / BN, KSPLIT);  // 8 x 4 x 8 = 256 CTAs
    gemm_kernel<<<gdim, 256>>>(out);
}